// round 16
// baseline (speedup 1.0000x reference)
#include <cuda_runtime.h>
#include <math.h>

#define LSEQ 4096
#define DD   192
#define BB   2
#define TOT  (BB*LSEQ*DD)
#define LOG2E 1.4426950408889634f

// ---------------- scratch ----------------
__device__ __align__(16) float2 g_BC[TOT];   // [b][l][n] -> (B, C)
__device__ __align__(16) float2 g_dd[TOT];   // [b][d][l] -> (delta, delta*u)
__device__ __align__(16) float  g_uT[TOT];   // [b][d][l]

// ---------------- helpers ----------------
__device__ __forceinline__ float ex2f(float x) {
    float y;
    asm("ex2.approx.ftz.f32 %0, %1;" : "=f"(y) : "f"(x));
    return y;
}
__device__ __forceinline__ float softplus_f(float x) {
    if (x > 20.0f) return x;
    return log1pf(expf(x));
}
__device__ __forceinline__ void cp16(float* smem_dst, const float* gmem_src) {
    unsigned s = (unsigned)__cvta_generic_to_shared(smem_dst);
    asm volatile("cp.async.cg.shared.global [%0], [%1], 16;\n" :: "r"(s), "l"(gmem_src));
}
__device__ __forceinline__ void cp_commit() { asm volatile("cp.async.commit_group;\n" ::: "memory"); }
__device__ __forceinline__ void cp_wait0()  { asm volatile("cp.async.wait_group 0;\n" ::: "memory"); }

// ---------------- K1: merged tokenize + all three projections (unchanged) ----------------
__global__ void proj_kernel(const float* __restrict__ x,
                            const float* __restrict__ W_B, const float* __restrict__ b_B,
                            const float* __restrict__ W_C, const float* __restrict__ b_C,
                            const float* __restrict__ W_dt, const float* __restrict__ b_dt) {
    __shared__ __align__(16) float As[16][128];
    __shared__ __align__(16) float Bs[16][64];
    __shared__ __align__(16) float Cs[16][64];

    int tid = threadIdx.x;
    int tx = tid & 15;
    int ty = tid >> 4;
    int m0 = blockIdx.x * 128;
    int by = blockIdx.y;
    bool isBC = (by < 3);
    int jw0 = (isBC ? by : by - 3) * 64;

    float accB[8][4], accC[8][4];
#pragma unroll
    for (int i = 0; i < 8; i++)
#pragma unroll
        for (int j = 0; j < 4; j++) { accB[i][j] = 0.0f; accC[i][j] = 0.0f; }

    for (int kt = 0; kt < 12; kt++) {
        int k0 = kt * 16;
#pragma unroll
        for (int r = 0; r < 2; r++) {
            int idx  = tid + r * 256;
            int mrow = idx >> 2;
            int kq   = idx & 3;
            int m = m0 + mrow;
            int b = m >> 12;
            int l = m & 4095;
            int ih = l >> 6;
            int iw = l & 63;
            int c  = (k0 >> 2) + kq;
            const float* xb = x + (((b * 48 + c) * 128 + ih * 2) * 128 + iw * 2);
            float2 v01 = *(const float2*)xb;
            float2 v23 = *(const float2*)(xb + 128);
            As[kq * 4 + 0][mrow] = v01.x;
            As[kq * 4 + 1][mrow] = v01.y;
            As[kq * 4 + 2][mrow] = v23.x;
            As[kq * 4 + 3][mrow] = v23.y;
        }
        {
            int jrow = tid >> 2;
            int kq   = tid & 3;
            const float* W1 = isBC ? W_B : W_dt;
            float4 vb = *(const float4*)&W1[(jw0 + jrow) * 192 + k0 + kq * 4];
            Bs[kq * 4 + 0][jrow] = vb.x; Bs[kq * 4 + 1][jrow] = vb.y;
            Bs[kq * 4 + 2][jrow] = vb.z; Bs[kq * 4 + 3][jrow] = vb.w;
            if (isBC) {
                float4 vc = *(const float4*)&W_C[(jw0 + jrow) * 192 + k0 + kq * 4];
                Cs[kq * 4 + 0][jrow] = vc.x; Cs[kq * 4 + 1][jrow] = vc.y;
                Cs[kq * 4 + 2][jrow] = vc.z; Cs[kq * 4 + 3][jrow] = vc.w;
            }
        }
        __syncthreads();
        if (isBC) {
#pragma unroll
            for (int kk = 0; kk < 16; kk++) {
                float4 a0 = *(const float4*)&As[kk][ty * 8];
                float4 a1 = *(const float4*)&As[kk][ty * 8 + 4];
                float4 bv = *(const float4*)&Bs[kk][tx * 4];
                float4 cv = *(const float4*)&Cs[kk][tx * 4];
                float a[8] = {a0.x, a0.y, a0.z, a0.w, a1.x, a1.y, a1.z, a1.w};
                float bb[4] = {bv.x, bv.y, bv.z, bv.w};
                float cc[4] = {cv.x, cv.y, cv.z, cv.w};
#pragma unroll
                for (int i = 0; i < 8; i++)
#pragma unroll
                    for (int j = 0; j < 4; j++) {
                        accB[i][j] = fmaf(a[i], bb[j], accB[i][j]);
                        accC[i][j] = fmaf(a[i], cc[j], accC[i][j]);
                    }
            }
        } else {
#pragma unroll
            for (int kk = 0; kk < 16; kk++) {
                float4 a0 = *(const float4*)&As[kk][ty * 8];
                float4 a1 = *(const float4*)&As[kk][ty * 8 + 4];
                float4 bv = *(const float4*)&Bs[kk][tx * 4];
                float a[8] = {a0.x, a0.y, a0.z, a0.w, a1.x, a1.y, a1.z, a1.w};
                float bb[4] = {bv.x, bv.y, bv.z, bv.w};
#pragma unroll
                for (int i = 0; i < 8; i++)
#pragma unroll
                    for (int j = 0; j < 4; j++)
                        accB[i][j] = fmaf(a[i], bb[j], accB[i][j]);
            }
        }
        __syncthreads();
    }

    int ncol = jw0 + tx * 4;
    if (isBC) {
        float4 bB4 = *(const float4*)&b_B[ncol];
        float4 bC4 = *(const float4*)&b_C[ncol];
#pragma unroll
        for (int i = 0; i < 8; i++) {
            int m = m0 + ty * 8 + i;
            float4 o01, o23;
            o01.x = accB[i][0] + bB4.x; o01.y = accC[i][0] + bC4.x;
            o01.z = accB[i][1] + bB4.y; o01.w = accC[i][1] + bC4.y;
            o23.x = accB[i][2] + bB4.z; o23.y = accC[i][2] + bC4.z;
            o23.z = accB[i][3] + bB4.w; o23.w = accC[i][3] + bC4.w;
            *(float4*)&g_BC[m * 192 + ncol]     = o01;
            *(float4*)&g_BC[m * 192 + ncol + 2] = o23;
        }
    } else {
        float bd[4];
#pragma unroll
        for (int j = 0; j < 4; j++) bd[j] = b_dt[ncol + j];
        int c2 = ncol >> 2;
#pragma unroll
        for (int i = 0; i < 8; i++) {
            int m = m0 + ty * 8 + i;
            int b = m >> 12;
            int l = m & 4095;
            int ih = l >> 6;
            int iw = l & 63;
            const float* xb = x + (((b * 48 + c2) * 128 + ih * 2) * 128 + iw * 2);
            float uvals[4];
            uvals[0] = xb[0];
            uvals[1] = xb[1];
            uvals[2] = xb[128];
            uvals[3] = xb[129];
#pragma unroll
            for (int j = 0; j < 4; j++) {
                int dfeat = ncol + j;
                float lin = accB[i][j] + bd[j];
                float dt  = softplus_f(lin);
                float del = softplus_f(dt + bd[j]);
                float u   = uvals[j];
                int o = (b * 192 + dfeat) * LSEQ + l;
                g_dd[o] = make_float2(del, del * u);
                g_uT[o] = u;
            }
        }
    }
}

// ---------------- K2: selective scan, CH=64, 4 d's/block ----------------
// 96 blocks x 384 threads (12 warps, 3/SMSP balanced). Block: b = blk/48, dbase = (blk%48)*4.
// warp w: dl = w/3 (0..3), g = w%3; lane owns state pair n = g*64+2*lane for d = dbase+dl.
// BC smem tile (per-batch data) is shared by all 4 d's -> fill cost amortized 4x.
#define CH   64

__global__ void __launch_bounds__(384, 1)
scan_kernel(const float* __restrict__ A_log, const float* __restrict__ Dp,
            float* __restrict__ out) {
    extern __shared__ __align__(16) float S[];
    float*  BCf  = S;                        // [2][CH*384] = 49152
    float*  PS3  = S + 49152;                // [2 buf][2 sub][3 g][128] = 1536
    float2* DDsm = (float2*)(PS3 + 1536);    // [2][4][CH] float2 = 1024 f
    float*  Dpsm = (float*)(DDsm + 512);     // [4]

    int tid  = threadIdx.x;
    int w    = tid >> 5;
    int lane = tid & 31;
    int dl   = w / 3;          // d_local 0..3
    int g    = w - dl * 3;     // state group 0..2
    int b = blockIdx.x / 48;
    int dbase = (blockIdx.x % 48) * 4;
    int d = dbase + dl;

    int n0 = g * 64 + 2 * lane;
    float A20 = -expf(A_log[d * 192 + n0])     * LOG2E;
    float A21 = -expf(A_log[d * 192 + n0 + 1]) * LOG2E;
    float h0 = 0.0f, h1 = 0.0f;
    if (tid < 4) Dpsm[tid] = Dp[dbase + tid];
    const float SILU1 = 0.73105857863000489f;

    int edl = tid >> 5;        // epilogue d_local (tid<128)
    int es  = tid & 31;
    const float* usrc = g_uT + (b * 192 + dbase + edl) * LSEQ + es;

    const float* BCsrc = (const float*)(g_BC + b * LSEQ * 192);

    float u_cur0 = 0.0f, u_cur1 = 0.0f;
    // prologue: chunk 0
    {
        for (int t = tid; t < 6144; t += 384)
            cp16(BCf + t * 4, BCsrc + t * 4);
        cp_commit();
        if (tid < 128) { u_cur0 = usrc[0]; u_cur1 = usrc[32]; }
        if (w >= 8) {   // warps 8..11 load DD chunk 0 for d_local = w-8
            const float2* dsrc = g_dd + (b * 192 + dbase + (w - 8)) * LSEQ;
            DDsm[(w - 8) * CH + lane]      = dsrc[lane];
            DDsm[(w - 8) * CH + 32 + lane] = dsrc[32 + lane];
        }
        cp_wait0();
    }
    __syncthreads();

    const int NCHUNK = LSEQ / CH;
    for (int c = 0; c < NCHUNK; c++) {
        int l0  = c * CH;
        int buf = c & 1;

        float2 ddn0 = make_float2(0.f, 0.f), ddn1 = make_float2(0.f, 0.f);
        float u_nxt0 = 0.0f, u_nxt1 = 0.0f;
        if (c + 1 < NCHUNK) {
            const float* bsrc = BCsrc + (l0 + CH) * 384;
            float* bdst = BCf + (buf ^ 1) * 24576;
            for (int t = tid; t < 6144; t += 384)
                cp16(bdst + t * 4, bsrc + t * 4);
            cp_commit();
            if (tid < 128) { u_nxt0 = usrc[l0 + CH]; u_nxt1 = usrc[l0 + CH + 32]; }
            if (w >= 8) {
                const float2* dsrc = g_dd + (b * 192 + dbase + (w - 8)) * LSEQ + l0 + CH;
                ddn0 = dsrc[lane];
                ddn1 = dsrc[32 + lane];
            }
        }

        // ---- two 32-step register bursts ----
#pragma unroll
        for (int sub = 0; sub < 2; sub++) {
            float acc[32];
            const float4* bcp = (const float4*)(BCf + buf * 24576) + sub * 32 * 96 + g * 32 + lane;
            const float2* DDc = DDsm + buf * 256 + dl * CH + sub * 32;
#pragma unroll
            for (int s = 0; s < 32; s++) {
                float2 dd = DDc[s];
                float4 bc = bcp[s * 96];
                float e0 = ex2f(dd.x * A20);
                float e1 = ex2f(dd.x * A21);
                h0 = fmaf(e0, h0, dd.y * bc.x);
                h1 = fmaf(e1, h1, dd.y * bc.z);
                acc[s] = fmaf(h0, bc.y, h1 * bc.w);
            }
            // butterfly: reduce over lanes + transpose (lane l -> step l)
#pragma unroll
            for (int m = 16; m >= 1; m >>= 1) {
                bool hi = (lane & m) != 0;
#pragma unroll
                for (int j = 0; j < m; j++) {
                    float send = hi ? acc[j] : acc[j + m];
                    float recv = __shfl_xor_sync(0xffffffffu, send, m);
                    float keep = hi ? acc[j + m] : acc[j];
                    acc[j] = keep + recv;
                }
            }
            PS3[buf * 768 + sub * 384 + g * 128 + dl * 32 + lane] = acc[0];
        }

        if (w >= 8 && c + 1 < NCHUNK) {
            DDsm[(buf ^ 1) * 256 + (w - 8) * CH + lane]      = ddn0;
            DDsm[(buf ^ 1) * 256 + (w - 8) * CH + 32 + lane] = ddn1;
        }

        cp_wait0();
        __syncthreads();

        // ---- cross-warp sum + epilogue (tid<128): 2 steps per thread ----
        if (tid < 128) {
#pragma unroll
            for (int sub = 0; sub < 2; sub++) {
                int base = buf * 768 + sub * 384 + tid;
                float sum = PS3[base] + PS3[base + 128] + PS3[base + 256];
                float uu  = sub ? u_cur1 : u_cur0;
                float val = (sum + Dpsm[edl] * uu) * SILU1;

                int dd_ = dbase + edl;
                int l = l0 + sub * 32 + es;
                int flat = dd_ * LSEQ + l;
                int i1   = flat / 12288;
                int rem  = flat - i1 * 12288;
                int i2   = rem / 192;
                int r2   = rem - i2 * 192;
                int i3   = r2 >> 2;
                int i4   = (r2 >> 1) & 1;
                int i5   = r2 & 1;
                out[((b * 48 + i3) * 128 + i1 * 2 + i4) * 128 + i2 * 2 + i5] = val;
            }
        }
        u_cur0 = u_nxt0;
        u_cur1 = u_nxt1;
    }
}

// ---------------- launch ----------------
extern "C" void kernel_launch(void* const* d_in, const int* in_sizes, int n_in,
                              void* d_out, int out_size) {
    (void)in_sizes; (void)n_in; (void)out_size;
    const float* x     = (const float*)d_in[0];
    const float* A_log = (const float*)d_in[1];
    const float* Dp    = (const float*)d_in[2];
    const float* W_B   = (const float*)d_in[3];
    const float* b_B   = (const float*)d_in[4];
    const float* W_C   = (const float*)d_in[5];
    const float* b_C   = (const float*)d_in[6];
    const float* W_dt  = (const float*)d_in[7];
    const float* b_dt  = (const float*)d_in[8];
    float* out = (float*)d_out;

    // smem floats: BC 49152 + PS3 1536 + DD 1024 + Dp 4 = 51716 (~202KB)
    int smem = (49152 + 1536 + 1024 + 4) * (int)sizeof(float);
    static int attr_set = 0;
    if (!attr_set) {
        cudaFuncSetAttribute(scan_kernel, cudaFuncAttributeMaxDynamicSharedMemorySize, smem);
        attr_set = 1;
    }

    dim3 gp(64, 6);
    proj_kernel<<<gp, 256>>>(x, W_B, b_B, W_C, b_C, W_dt, b_dt);
    scan_kernel<<<96, 384, smem>>>(A_log, Dp, out);
}

// round 17
// speedup vs baseline: 1.1117x; 1.1117x over previous
#include <cuda_runtime.h>
#include <math.h>

#define LSEQ 4096
#define DD   192
#define BB   2
#define TOT  (BB*LSEQ*DD)
#define LOG2E 1.4426950408889634f

// ---------------- scratch ----------------
__device__ __align__(16) float2 g_BC[TOT];   // [b][l][n] -> (B, C)
__device__ __align__(16) float2 g_dd[TOT];   // [b][d][l] -> (delta, delta*u)
__device__ __align__(16) float  g_uT[TOT];   // [b][d][l]

// ---------------- helpers ----------------
__device__ __forceinline__ float ex2f(float x) {
    float y;
    asm("ex2.approx.ftz.f32 %0, %1;" : "=f"(y) : "f"(x));
    return y;
}
__device__ __forceinline__ float softplus_f(float x) {
    if (x > 20.0f) return x;
    return log1pf(expf(x));
}
__device__ __forceinline__ void cp16(float* smem_dst, const float* gmem_src) {
    unsigned s = (unsigned)__cvta_generic_to_shared(smem_dst);
    asm volatile("cp.async.cg.shared.global [%0], [%1], 16;\n" :: "r"(s), "l"(gmem_src));
}
__device__ __forceinline__ void cp_commit() { asm volatile("cp.async.commit_group;\n" ::: "memory"); }
__device__ __forceinline__ void cp_wait0()  { asm volatile("cp.async.wait_group 0;\n" ::: "memory"); }

// ---------------- K1: merged tokenize + projections, register-staged pipeline ----------------
// blockIdx.y < 3: (B,C) interleaved output; blockIdx.y >= 3: dt path.
// Per k-tile: LDG next tile -> regs | compute current from smem[buf] | STS regs -> smem[buf^1] | 1 barrier.
__global__ void proj_kernel(const float* __restrict__ x,
                            const float* __restrict__ W_B, const float* __restrict__ b_B,
                            const float* __restrict__ W_C, const float* __restrict__ b_C,
                            const float* __restrict__ W_dt, const float* __restrict__ b_dt) {
    __shared__ __align__(16) float As[2][16][128];
    __shared__ __align__(16) float Bs[2][16][64];
    __shared__ __align__(16) float Cs[2][16][64];

    int tid = threadIdx.x;
    int tx = tid & 15;
    int ty = tid >> 4;
    int m0 = blockIdx.x * 128;
    int by = blockIdx.y;
    bool isBC = (by < 3);
    int jw0 = (isBC ? by : by - 3) * 64;

    // per-thread gather bases for the A tile (2 quads per thread)
    const float* xbase[2];
    int mrow_r[2], kq_r[2];
#pragma unroll
    for (int r = 0; r < 2; r++) {
        int idx  = tid + r * 256;
        int mrow = idx >> 2;
        int kq   = idx & 3;
        int m = m0 + mrow;
        int b = m >> 12;
        int l = m & 4095;
        int ih = l >> 6;
        int iw = l & 63;
        xbase[r] = x + (((b * 48 + kq) * 128 + ih * 2) * 128 + iw * 2);
        mrow_r[r] = mrow;
        kq_r[r] = kq;
    }
    // weight tile base (1 float4 per matrix per thread)
    int jrow = tid >> 2;
    int kq2  = tid & 3;
    const float* Wb_base = (isBC ? W_B : W_dt) + (jw0 + jrow) * 192 + kq2 * 4;
    const float* Wc_base = W_C + (jw0 + jrow) * 192 + kq2 * 4;

    float accB[8][4], accC[8][4];
#pragma unroll
    for (int i = 0; i < 8; i++)
#pragma unroll
        for (int j = 0; j < 4; j++) { accB[i][j] = 0.0f; accC[i][j] = 0.0f; }

    // staging registers
    float2 a01[2], a23[2];
    float4 wb, wc;

    // load tile 0
#pragma unroll
    for (int r = 0; r < 2; r++) {
        const float* src = xbase[r];
        a01[r] = *(const float2*)src;
        a23[r] = *(const float2*)(src + 128);
    }
    wb = *(const float4*)Wb_base;
    if (isBC) wc = *(const float4*)Wc_base;
    // store tile 0 -> buf 0
#pragma unroll
    for (int r = 0; r < 2; r++) {
        int kq = kq_r[r], mr = mrow_r[r];
        As[0][kq * 4 + 0][mr] = a01[r].x;
        As[0][kq * 4 + 1][mr] = a01[r].y;
        As[0][kq * 4 + 2][mr] = a23[r].x;
        As[0][kq * 4 + 3][mr] = a23[r].y;
    }
    Bs[0][kq2 * 4 + 0][jrow] = wb.x; Bs[0][kq2 * 4 + 1][jrow] = wb.y;
    Bs[0][kq2 * 4 + 2][jrow] = wb.z; Bs[0][kq2 * 4 + 3][jrow] = wb.w;
    if (isBC) {
        Cs[0][kq2 * 4 + 0][jrow] = wc.x; Cs[0][kq2 * 4 + 1][jrow] = wc.y;
        Cs[0][kq2 * 4 + 2][jrow] = wc.z; Cs[0][kq2 * 4 + 3][jrow] = wc.w;
    }
    __syncthreads();

    for (int kt = 0; kt < 12; kt++) {
        int buf = kt & 1;
        if (kt + 1 < 12) {
            // issue next tile's LDGs (overlap with compute below)
#pragma unroll
            for (int r = 0; r < 2; r++) {
                const float* src = xbase[r] + (kt + 1) * 65536;  // 4 channels * 16384
                a01[r] = *(const float2*)src;
                a23[r] = *(const float2*)(src + 128);
            }
            wb = *(const float4*)(Wb_base + (kt + 1) * 16);
            if (isBC) wc = *(const float4*)(Wc_base + (kt + 1) * 16);
        }

        if (isBC) {
#pragma unroll
            for (int kk = 0; kk < 16; kk++) {
                float4 a0 = *(const float4*)&As[buf][kk][ty * 8];
                float4 a1 = *(const float4*)&As[buf][kk][ty * 8 + 4];
                float4 bv = *(const float4*)&Bs[buf][kk][tx * 4];
                float4 cv = *(const float4*)&Cs[buf][kk][tx * 4];
                float a[8] = {a0.x, a0.y, a0.z, a0.w, a1.x, a1.y, a1.z, a1.w};
                float bb[4] = {bv.x, bv.y, bv.z, bv.w};
                float cc[4] = {cv.x, cv.y, cv.z, cv.w};
#pragma unroll
                for (int i = 0; i < 8; i++)
#pragma unroll
                    for (int j = 0; j < 4; j++) {
                        accB[i][j] = fmaf(a[i], bb[j], accB[i][j]);
                        accC[i][j] = fmaf(a[i], cc[j], accC[i][j]);
                    }
            }
        } else {
#pragma unroll
            for (int kk = 0; kk < 16; kk++) {
                float4 a0 = *(const float4*)&As[buf][kk][ty * 8];
                float4 a1 = *(const float4*)&As[buf][kk][ty * 8 + 4];
                float4 bv = *(const float4*)&Bs[buf][kk][tx * 4];
                float a[8] = {a0.x, a0.y, a0.z, a0.w, a1.x, a1.y, a1.z, a1.w};
                float bb[4] = {bv.x, bv.y, bv.z, bv.w};
#pragma unroll
                for (int i = 0; i < 8; i++)
#pragma unroll
                    for (int j = 0; j < 4; j++)
                        accB[i][j] = fmaf(a[i], bb[j], accB[i][j]);
            }
        }

        if (kt + 1 < 12) {
            int nb = buf ^ 1;
#pragma unroll
            for (int r = 0; r < 2; r++) {
                int kq = kq_r[r], mr = mrow_r[r];
                As[nb][kq * 4 + 0][mr] = a01[r].x;
                As[nb][kq * 4 + 1][mr] = a01[r].y;
                As[nb][kq * 4 + 2][mr] = a23[r].x;
                As[nb][kq * 4 + 3][mr] = a23[r].y;
            }
            Bs[nb][kq2 * 4 + 0][jrow] = wb.x; Bs[nb][kq2 * 4 + 1][jrow] = wb.y;
            Bs[nb][kq2 * 4 + 2][jrow] = wb.z; Bs[nb][kq2 * 4 + 3][jrow] = wb.w;
            if (isBC) {
                Cs[nb][kq2 * 4 + 0][jrow] = wc.x; Cs[nb][kq2 * 4 + 1][jrow] = wc.y;
                Cs[nb][kq2 * 4 + 2][jrow] = wc.z; Cs[nb][kq2 * 4 + 3][jrow] = wc.w;
            }
            __syncthreads();
        }
    }

    int ncol = jw0 + tx * 4;
    if (isBC) {
        float4 bB4 = *(const float4*)&b_B[ncol];
        float4 bC4 = *(const float4*)&b_C[ncol];
#pragma unroll
        for (int i = 0; i < 8; i++) {
            int m = m0 + ty * 8 + i;
            float4 o01, o23;
            o01.x = accB[i][0] + bB4.x; o01.y = accC[i][0] + bC4.x;
            o01.z = accB[i][1] + bB4.y; o01.w = accC[i][1] + bC4.y;
            o23.x = accB[i][2] + bB4.z; o23.y = accC[i][2] + bC4.z;
            o23.z = accB[i][3] + bB4.w; o23.w = accC[i][3] + bC4.w;
            *(float4*)&g_BC[m * 192 + ncol]     = o01;
            *(float4*)&g_BC[m * 192 + ncol + 2] = o23;
        }
    } else {
        float bd[4];
#pragma unroll
        for (int j = 0; j < 4; j++) bd[j] = b_dt[ncol + j];
        int c2 = ncol >> 2;
#pragma unroll
        for (int i = 0; i < 8; i++) {
            int m = m0 + ty * 8 + i;
            int b = m >> 12;
            int l = m & 4095;
            int ih = l >> 6;
            int iw = l & 63;
            const float* xb = x + (((b * 48 + c2) * 128 + ih * 2) * 128 + iw * 2);
            float uvals[4];
            uvals[0] = xb[0];
            uvals[1] = xb[1];
            uvals[2] = xb[128];
            uvals[3] = xb[129];
#pragma unroll
            for (int j = 0; j < 4; j++) {
                int dfeat = ncol + j;
                float lin = accB[i][j] + bd[j];
                float dt  = softplus_f(lin);
                float del = softplus_f(dt + bd[j]);
                float u   = uvals[j];
                int o = (b * 192 + dfeat) * LSEQ + l;
                g_dd[o] = make_float2(del, del * u);
                g_uT[o] = u;
            }
        }
    }
}

// ---------------- K2: selective scan, CH=64 (exact round-15 kernel: 128 blocks, 3 d's) ----------------
#define CH   64

__global__ void __launch_bounds__(288, 1)
scan_kernel(const float* __restrict__ A_log, const float* __restrict__ Dp,
            float* __restrict__ out) {
    extern __shared__ __align__(16) float S[];
    float*  BCf  = S;                        // [2][CH*384] = 49152
    float*  PS3  = S + 49152;                // [2][2 sub][3 g][96] = 1152
    float2* DDsm = (float2*)(PS3 + 1152);    // [2][3][CH] float2 = 768 f2
    float*  Dpsm = (float*)(DDsm + 384);     // [3]+pad

    int tid  = threadIdx.x;
    int w    = tid >> 5;
    int lane = tid & 31;
    int dl   = w / 3;
    int g    = w - dl * 3;
    int b = blockIdx.x >> 6;
    int dbase = (blockIdx.x & 63) * 3;
    int d = dbase + dl;

    int n0 = g * 64 + 2 * lane;
    float A20 = -expf(A_log[d * 192 + n0])     * LOG2E;
    float A21 = -expf(A_log[d * 192 + n0 + 1]) * LOG2E;
    float h0 = 0.0f, h1 = 0.0f;
    if (tid < 3) Dpsm[tid] = Dp[dbase + tid];
    const float SILU1 = 0.73105857863000489f;

    int edl = tid >> 5;
    int es  = tid & 31;
    const float* usrc = g_uT + (b * 192 + dbase + edl) * LSEQ + es;

    const float* BCsrc = (const float*)(g_BC + b * LSEQ * 192);

    float u_cur0 = 0.0f, u_cur1 = 0.0f;
    // prologue: chunk 0
    {
        for (int t = tid; t < 6144; t += 288)
            cp16(BCf + t * 4, BCsrc + t * 4);
        cp_commit();
        if (tid < 96) { u_cur0 = usrc[0]; u_cur1 = usrc[32]; }
        if (w >= 6) {
            const float2* dsrc = g_dd + (b * 192 + dbase + (w - 6)) * LSEQ;
            DDsm[(w - 6) * CH + lane]      = dsrc[lane];
            DDsm[(w - 6) * CH + 32 + lane] = dsrc[32 + lane];
        }
        cp_wait0();
    }
    __syncthreads();

    const int NCHUNK = LSEQ / CH;
    for (int c = 0; c < NCHUNK; c++) {
        int l0  = c * CH;
        int buf = c & 1;

        float2 ddn0 = make_float2(0.f, 0.f), ddn1 = make_float2(0.f, 0.f);
        float u_nxt0 = 0.0f, u_nxt1 = 0.0f;
        if (c + 1 < NCHUNK) {
            const float* bsrc = BCsrc + (l0 + CH) * 384;
            float* bdst = BCf + (buf ^ 1) * 24576;
            for (int t = tid; t < 6144; t += 288)
                cp16(bdst + t * 4, bsrc + t * 4);
            cp_commit();
            if (tid < 96) { u_nxt0 = usrc[l0 + CH]; u_nxt1 = usrc[l0 + CH + 32]; }
            if (w >= 6) {
                const float2* dsrc = g_dd + (b * 192 + dbase + (w - 6)) * LSEQ + l0 + CH;
                ddn0 = dsrc[lane];
                ddn1 = dsrc[32 + lane];
            }
        }

        // ---- two 32-step register bursts ----
#pragma unroll
        for (int sub = 0; sub < 2; sub++) {
            float acc[32];
            const float4* bcp = (const float4*)(BCf + buf * 24576) + sub * 32 * 96 + g * 32 + lane;
            const float2* DDc = DDsm + buf * 192 + dl * CH + sub * 32;
#pragma unroll
            for (int s = 0; s < 32; s++) {
                float2 dd = DDc[s];
                float4 bc = bcp[s * 96];
                float e0 = ex2f(dd.x * A20);
                float e1 = ex2f(dd.x * A21);
                h0 = fmaf(e0, h0, dd.y * bc.x);
                h1 = fmaf(e1, h1, dd.y * bc.z);
                acc[s] = fmaf(h0, bc.y, h1 * bc.w);
            }
            // butterfly: reduce over lanes + transpose (lane l -> step l)
#pragma unroll
            for (int m = 16; m >= 1; m >>= 1) {
                bool hi = (lane & m) != 0;
#pragma unroll
                for (int j = 0; j < m; j++) {
                    float send = hi ? acc[j] : acc[j + m];
                    float recv = __shfl_xor_sync(0xffffffffu, send, m);
                    float keep = hi ? acc[j + m] : acc[j];
                    acc[j] = keep + recv;
                }
            }
            PS3[buf * 576 + sub * 288 + g * 96 + dl * 32 + lane] = acc[0];
        }

        if (w >= 6 && c + 1 < NCHUNK) {
            DDsm[(buf ^ 1) * 192 + (w - 6) * CH + lane]      = ddn0;
            DDsm[(buf ^ 1) * 192 + (w - 6) * CH + 32 + lane] = ddn1;
        }

        cp_wait0();
        __syncthreads();

        // ---- cross-warp sum + epilogue (tid<96): 2 steps per thread ----
        if (tid < 96) {
#pragma unroll
            for (int sub = 0; sub < 2; sub++) {
                int base = buf * 576 + sub * 288 + tid;
                float sum = PS3[base] + PS3[base + 96] + PS3[base + 192];
                float uu  = sub ? u_cur1 : u_cur0;
                float val = (sum + Dpsm[edl] * uu) * SILU1;

                int dd_ = dbase + edl;
                int l = l0 + sub * 32 + es;
                int flat = dd_ * LSEQ + l;
                int i1   = flat / 12288;
                int rem  = flat - i1 * 12288;
                int i2   = rem / 192;
                int r2   = rem - i2 * 192;
                int i3   = r2 >> 2;
                int i4   = (r2 >> 1) & 1;
                int i5   = r2 & 1;
                out[((b * 48 + i3) * 128 + i1 * 2 + i4) * 128 + i2 * 2 + i5] = val;
            }
        }
        u_cur0 = u_nxt0;
        u_cur1 = u_nxt1;
    }
}

// ---------------- launch ----------------
extern "C" void kernel_launch(void* const* d_in, const int* in_sizes, int n_in,
                              void* d_out, int out_size) {
    (void)in_sizes; (void)n_in; (void)out_size;
    const float* x     = (const float*)d_in[0];
    const float* A_log = (const float*)d_in[1];
    const float* Dp    = (const float*)d_in[2];
    const float* W_B   = (const float*)d_in[3];
    const float* b_B   = (const float*)d_in[4];
    const float* W_C   = (const float*)d_in[5];
    const float* b_C   = (const float*)d_in[6];
    const float* W_dt  = (const float*)d_in[7];
    const float* b_dt  = (const float*)d_in[8];
    float* out = (float*)d_out;

    // smem floats: BC 49152 + PS3 1152 + DD 768 + Dp 4 = 51076 (~204KB)
    int smem = (49152 + 1152 + 768 + 4) * (int)sizeof(float);
    static int attr_set = 0;
    if (!attr_set) {
        cudaFuncSetAttribute(scan_kernel, cudaFuncAttributeMaxDynamicSharedMemorySize, smem);
        attr_set = 1;
    }

    dim3 gp(64, 6);
    proj_kernel<<<gp, 256>>>(x, W_B, b_B, W_C, b_C, W_dt, b_dt);
    scan_kernel<<<128, 288, smem>>>(A_log, Dp, out);
}